// round 12
// baseline (speedup 1.0000x reference)
#include <cuda_runtime.h>

#define D_CH 20
#define GV 128
#define NUM_EMB (GV * GV * GV)
#define NUM_BINS (GV * GV * 8)          // 131072 (brick-permuted)
#define MAXP (1 << 21)
#define SCAN_BLOCKS 512                 // 512 blocks x 256 = 131072

__device__ int    g_hist[NUM_BINS];
__device__ int    g_base[NUM_BINS];
__device__ int    g_blocksum[SCAN_BLOCKS];
__device__ float4 g_tmp[MAXP];          // (x,y,z, rank-bits)
__device__ float4 g_sorted[MAXP];       // (x,y,z, orig-bits)

// Brick key: brick = (gz/4, gy/4, gx/16) covering 16x * 4y * 4z = 256 cells
// (~122 pts). Bricks sweep x fastest; inner cells (gz&3, gy&3) minor.
// A 1024-thread gather block (204 pts) covers ~1.7 x-adjacent bricks ->
// compact 3D region -> within-block L1 reuse of vertex rows.
__device__ __forceinline__ int bin_of(float px, float py, float pz)
{
    int gx = (int)floorf((px + 1.0f) * 0.5f * (float)GV);
    int gy = (int)floorf((py + 1.0f) * 0.5f * (float)GV);
    int gz = (int)floorf((pz + 1.0f) * 0.5f * (float)GV);
    gx = min(max(gx, 0), GV - 1);
    gy = min(max(gy, 0), GV - 1);
    gz = min(max(gz, 0), GV - 1);
    int brick = ((gz >> 2) * 32 + (gy >> 2)) * 8 + (gx >> 4);
    int inner = ((gz & 3) << 2) | (gy & 3);
    return brick * 16 + inner;
}

__global__ void zero_kernel()
{
    int i = blockIdx.x * blockDim.x + threadIdx.x;
    if (i < NUM_BINS) g_hist[i] = 0;
}

// Pass 1 (4 pts/thread): count + per-point rank, stash point+rank in L2 temp.
__global__ void hist_rank_kernel(const float* __restrict__ x, int n)
{
    int p0 = (blockIdx.x * blockDim.x + threadIdx.x) * 4;
    if (p0 >= n) return;

    if (p0 + 4 <= n) {
        const float4* x4 = (const float4*)(x + (size_t)p0 * 3);
        float4 a = __ldg(&x4[0]);
        float4 b = __ldg(&x4[1]);
        float4 c = __ldg(&x4[2]);
        float pxs[4] = { a.x, a.w, b.z, c.y };
        float pys[4] = { a.y, b.x, b.w, c.z };
        float pzs[4] = { a.z, b.y, c.x, c.w };
        int bins[4];
        #pragma unroll
        for (int i = 0; i < 4; i++)
            bins[i] = bin_of(pxs[i], pys[i], pzs[i]);
        int ranks[4];
        #pragma unroll
        for (int i = 0; i < 4; i++)
            ranks[i] = atomicAdd(&g_hist[bins[i]], 1);
        #pragma unroll
        for (int i = 0; i < 4; i++)
            g_tmp[p0 + i] = make_float4(pxs[i], pys[i], pzs[i],
                                        __int_as_float(ranks[i]));
    } else {
        for (int p = p0; p < n; p++) {
            float px = __ldg(&x[p * 3 + 0]);
            float py = __ldg(&x[p * 3 + 1]);
            float pz = __ldg(&x[p * 3 + 2]);
            int bin  = bin_of(px, py, pz);
            int rank = atomicAdd(&g_hist[bin], 1);
            g_tmp[p] = make_float4(px, py, pz, __int_as_float(rank));
        }
    }
}

// Scan stage A: per-block sums of 256 bins (warp intrinsics, 1 barrier).
__global__ void scanA_kernel()
{
    __shared__ int wsum[8];
    int tid = threadIdx.x;
    int v = g_hist[blockIdx.x * 256 + tid];
    int ws = __reduce_add_sync(0xFFFFFFFFu, v);
    if ((tid & 31) == 0) wsum[tid >> 5] = ws;
    __syncthreads();
    if (tid < 32) {
        int s = (tid < 8) ? wsum[tid] : 0;
        s = __reduce_add_sync(0xFFFFFFFFu, s);
        if (tid == 0) g_blocksum[blockIdx.x] = s;
    }
}

// Scan stage C (B folded in): block base = sum(blocksums[0..b)), then
// warp-shuffle exclusive scan of this block's 256 bins.
__global__ void scanC_kernel()
{
    __shared__ int wsum[8];      // per-warp scan sums
    __shared__ int bsum[8];      // block-base partial sums
    const int tid  = threadIdx.x;
    const int lane = tid & 31;
    const int wrp  = tid >> 5;
    const int b    = blockIdx.x;

    int s0 = (tid       < b) ? g_blocksum[tid]       : 0;
    int s1 = (tid + 256 < b) ? g_blocksum[tid + 256] : 0;
    int bs = __reduce_add_sync(0xFFFFFFFFu, s0 + s1);
    if (lane == 0) bsum[wrp] = bs;

    int i = b * 256 + tid;
    int v = g_hist[i];
    int incl = v;
    #pragma unroll
    for (int off = 1; off < 32; off <<= 1) {
        int t = __shfl_up_sync(0xFFFFFFFFu, incl, off);
        if (lane >= off) incl += t;
    }
    if (lane == 31) wsum[wrp] = incl;
    __syncthreads();

    int blockbase = 0;
    #pragma unroll
    for (int w = 0; w < 8; w++) {
        blockbase += bsum[w];
        if (w < wrp) blockbase += wsum[w];
    }
    g_base[i] = blockbase + (incl - v);
}

// Pass 2 (4 pts/thread): atomic-free scatter, pos = base[bin] + rank.
__global__ void scatter_kernel(int n)
{
    int p0 = (blockIdx.x * blockDim.x + threadIdx.x) * 4;
    if (p0 >= n) return;
    int cnt = min(4, n - p0);
    #pragma unroll 4
    for (int i = 0; i < cnt; i++) {
        float4 t = g_tmp[p0 + i];
        int bin  = bin_of(t.x, t.y, t.z);
        int pos  = g_base[bin] + __float_as_int(t.w);
        g_sorted[pos] = make_float4(t.x, t.y, t.z, __int_as_float(p0 + i));
    }
}

__device__ __forceinline__ void interp_point(
    const float* __restrict__ grid, float* __restrict__ out,
    float px, float py, float pz, int orig, unsigned int c4)
{
    unsigned int cbase = c4 * 4u;

    int gx = (int)floorf((px + 1.0f) * 0.5f * (float)GV);
    int gy = (int)floorf((py + 1.0f) * 0.5f * (float)GV);
    int gz = (int)floorf((pz + 1.0f) * 0.5f * (float)GV);

    const float inv_v2 = 2.0f / (float)GV;   // exact in fp32
    float x1 = (float)gx * inv_v2 - 1.0f;
    float x2 = (float)(gx + 1) * inv_v2 - 1.0f;
    float y1 = (float)gy * inv_v2 - 1.0f;
    float y2 = (float)(gy + 1) * inv_v2 - 1.0f;
    float z1 = (float)gz * inv_v2 - 1.0f;
    float z2 = (float)(gz + 1) * inv_v2 - 1.0f;

    const float inv_den = 64.0f;             // 1/(2/128), exact
    float wx0 = (x2 - px) * inv_den;
    float wx1 = (px - x1) * inv_den;
    float wy0 = (y2 - py) * inv_den;
    float wy1 = (py - y1) * inv_den;
    float wz0 = (z2 - pz) * inv_den;
    float wz1 = (pz - z1) * inv_den;

    int base = gx + gy * GV + gz * GV * GV;
    const int maxi = NUM_EMB - 1;
    int f000 = min(base,                  maxi);
    int f100 = min(base + 1,              maxi);
    int f010 = min(base + GV,             maxi);
    int f110 = min(base + GV + 1,         maxi);
    int f001 = min(base + GV*GV,          maxi);
    int f101 = min(base + GV*GV + 1,      maxi);
    int f011 = min(base + GV*GV + GV,     maxi);
    int f111 = min(base + GV*GV + GV + 1, maxi);

    const float4* g4 = (const float4*)grid;
    float4 q000 = __ldg(&g4[((size_t)f000 * D_CH + cbase) >> 2]);
    float4 q100 = __ldg(&g4[((size_t)f100 * D_CH + cbase) >> 2]);
    float4 q010 = __ldg(&g4[((size_t)f010 * D_CH + cbase) >> 2]);
    float4 q110 = __ldg(&g4[((size_t)f110 * D_CH + cbase) >> 2]);
    float4 q001 = __ldg(&g4[((size_t)f001 * D_CH + cbase) >> 2]);
    float4 q101 = __ldg(&g4[((size_t)f101 * D_CH + cbase) >> 2]);
    float4 q011 = __ldg(&g4[((size_t)f011 * D_CH + cbase) >> 2]);
    float4 q111 = __ldg(&g4[((size_t)f111 * D_CH + cbase) >> 2]);

    float4 r;
    {
        float fx0 = wx0 * q000.x + wx1 * q100.x;
        float fx1 = wx0 * q010.x + wx1 * q110.x;
        float fx2 = wx0 * q001.x + wx1 * q101.x;
        float fx3 = wx0 * q011.x + wx1 * q111.x;
        r.x = wz0 * (wy0 * fx0 + wy1 * fx1) + wz1 * (wy0 * fx2 + wy1 * fx3);
    }
    {
        float fx0 = wx0 * q000.y + wx1 * q100.y;
        float fx1 = wx0 * q010.y + wx1 * q110.y;
        float fx2 = wx0 * q001.y + wx1 * q101.y;
        float fx3 = wx0 * q011.y + wx1 * q111.y;
        r.y = wz0 * (wy0 * fx0 + wy1 * fx1) + wz1 * (wy0 * fx2 + wy1 * fx3);
    }
    {
        float fx0 = wx0 * q000.z + wx1 * q100.z;
        float fx1 = wx0 * q010.z + wx1 * q110.z;
        float fx2 = wx0 * q001.z + wx1 * q101.z;
        float fx3 = wx0 * q011.z + wx1 * q111.z;
        r.z = wz0 * (wy0 * fx0 + wy1 * fx1) + wz1 * (wy0 * fx2 + wy1 * fx3);
    }
    {
        float fx0 = wx0 * q000.w + wx1 * q100.w;
        float fx1 = wx0 * q010.w + wx1 * q110.w;
        float fx2 = wx0 * q001.w + wx1 * q101.w;
        float fx3 = wx0 * q011.w + wx1 * q111.w;
        r.w = wz0 * (wy0 * fx0 + wy1 * fx1) + wz1 * (wy0 * fx2 + wy1 * fx3);
    }

    __stcs((float4*)out + (size_t)orig * 5u + c4, r);
}

// Gather in brick-sorted order: 5 threads/point, 1024-thread blocks so each
// block's ~204 points form a compact 3D region (within-block L1 reuse).
__global__ void __launch_bounds__(1024) gather_kernel(
    const float* __restrict__ grid,
    float* __restrict__ out,
    int n_pts)
{
    unsigned int gid = blockIdx.x * 1024u + threadIdx.x;
    unsigned int total = (unsigned int)n_pts * 5u;
    if (gid >= total) return;

    unsigned int sp = gid / 5u;
    unsigned int c4 = gid - sp * 5u;

    float4 pt = __ldg(&g_sorted[sp]);     // L2-resident (written by scatter)
    interp_point(grid, out, pt.x, pt.y, pt.z, __float_as_int(pt.w), c4);
}

// Fallback (unsorted) path if n_pts exceeds static scratch capacity.
__global__ void __launch_bounds__(256) gather_direct_kernel(
    const float* __restrict__ x,
    const float* __restrict__ grid,
    float* __restrict__ out,
    int n_pts)
{
    unsigned int gid = blockIdx.x * 256u + threadIdx.x;
    unsigned int total = (unsigned int)n_pts * 5u;
    if (gid >= total) return;
    unsigned int p = gid / 5u;
    unsigned int c4 = gid - p * 5u;
    float px = __ldg(&x[p * 3 + 0]);
    float py = __ldg(&x[p * 3 + 1]);
    float pz = __ldg(&x[p * 3 + 2]);
    interp_point(grid, out, px, py, pz, (int)p, c4);
}

extern "C" void kernel_launch(void* const* d_in, const int* in_sizes, int n_in,
                              void* d_out, int out_size)
{
    const float* x    = (const float*)d_in[0];
    const float* grid = (const float*)d_in[1];
    float* out        = (float*)d_out;

    int n_pts = in_sizes[0] / 3;

    if (n_pts > MAXP) {
        unsigned int total = (unsigned int)n_pts * 5u;
        gather_direct_kernel<<<(total + 255u) / 256u, 256>>>(x, grid, out, n_pts);
        return;
    }

    int pb4 = (n_pts + 1023) / 1024;       // 4 points per thread
    unsigned int total = (unsigned int)n_pts * 5u;

    zero_kernel<<<(NUM_BINS + 1023) / 1024, 1024>>>();
    hist_rank_kernel<<<pb4, 256>>>(x, n_pts);
    scanA_kernel<<<SCAN_BLOCKS, 256>>>();
    scanC_kernel<<<SCAN_BLOCKS, 256>>>();
    scatter_kernel<<<pb4, 256>>>(n_pts);
    gather_kernel<<<(total + 1023u) / 1024u, 1024>>>(grid, out, n_pts);
}

// round 13
// speedup vs baseline: 1.0106x; 1.0106x over previous
#include <cuda_runtime.h>

#define D_CH 20
#define GV 128
#define NUM_EMB (GV * GV * GV)
#define NUM_BINS (GV * GV * 8)          // 131072 = 8192 patches * 16 inner
#define NUM_PATCH 8192
#define MAXP (1 << 21)
#define SCAN_BLOCKS 512                 // 512 blocks x 256 = 131072

__device__ int    g_hist[NUM_BINS];
__device__ int    g_base[NUM_BINS];
__device__ int    g_blocksum[SCAN_BLOCKS];
__device__ float4 g_tmp[MAXP];          // (x,y,z, rank-bits)
__device__ float4 g_sorted[MAXP];       // (x,y,z, orig-bits)

// Patch key: patch = (gz/4, gy/4, gx/16) covering 16x * 4y * 4z = 256 cells
// (~122 pts); inner cell (gz&3, gy&3) minor. One gather block per patch.
__device__ __forceinline__ int bin_of(float px, float py, float pz)
{
    int gx = (int)floorf((px + 1.0f) * 0.5f * (float)GV);
    int gy = (int)floorf((py + 1.0f) * 0.5f * (float)GV);
    int gz = (int)floorf((pz + 1.0f) * 0.5f * (float)GV);
    gx = min(max(gx, 0), GV - 1);
    gy = min(max(gy, 0), GV - 1);
    gz = min(max(gz, 0), GV - 1);
    int patch = ((gz >> 2) * 32 + (gy >> 2)) * 8 + (gx >> 4);
    int inner = ((gz & 3) << 2) | (gy & 3);
    return patch * 16 + inner;
}

__global__ void zero_kernel()
{
    int i = blockIdx.x * blockDim.x + threadIdx.x;
    if (i < NUM_BINS) g_hist[i] = 0;
}

// Pass 1 (4 pts/thread): count + per-point rank, stash point+rank in L2 temp.
__global__ void hist_rank_kernel(const float* __restrict__ x, int n)
{
    int p0 = (blockIdx.x * blockDim.x + threadIdx.x) * 4;
    if (p0 >= n) return;

    if (p0 + 4 <= n) {
        const float4* x4 = (const float4*)(x + (size_t)p0 * 3);
        float4 a = __ldg(&x4[0]);
        float4 b = __ldg(&x4[1]);
        float4 c = __ldg(&x4[2]);
        float pxs[4] = { a.x, a.w, b.z, c.y };
        float pys[4] = { a.y, b.x, b.w, c.z };
        float pzs[4] = { a.z, b.y, c.x, c.w };
        int bins[4];
        #pragma unroll
        for (int i = 0; i < 4; i++)
            bins[i] = bin_of(pxs[i], pys[i], pzs[i]);
        int ranks[4];
        #pragma unroll
        for (int i = 0; i < 4; i++)
            ranks[i] = atomicAdd(&g_hist[bins[i]], 1);
        #pragma unroll
        for (int i = 0; i < 4; i++)
            g_tmp[p0 + i] = make_float4(pxs[i], pys[i], pzs[i],
                                        __int_as_float(ranks[i]));
    } else {
        for (int p = p0; p < n; p++) {
            float px = __ldg(&x[p * 3 + 0]);
            float py = __ldg(&x[p * 3 + 1]);
            float pz = __ldg(&x[p * 3 + 2]);
            int bin  = bin_of(px, py, pz);
            int rank = atomicAdd(&g_hist[bin], 1);
            g_tmp[p] = make_float4(px, py, pz, __int_as_float(rank));
        }
    }
}

// Scan stage A: per-block sums of 256 bins.
__global__ void scanA_kernel()
{
    __shared__ int wsum[8];
    int tid = threadIdx.x;
    int v = g_hist[blockIdx.x * 256 + tid];
    int ws = __reduce_add_sync(0xFFFFFFFFu, v);
    if ((tid & 31) == 0) wsum[tid >> 5] = ws;
    __syncthreads();
    if (tid < 32) {
        int s = (tid < 8) ? wsum[tid] : 0;
        s = __reduce_add_sync(0xFFFFFFFFu, s);
        if (tid == 0) g_blocksum[blockIdx.x] = s;
    }
}

// Scan stage C: block base = sum(blocksums[0..b)), then warp-shuffle scan.
__global__ void scanC_kernel()
{
    __shared__ int wsum[8];
    __shared__ int bsum[8];
    const int tid  = threadIdx.x;
    const int lane = tid & 31;
    const int wrp  = tid >> 5;
    const int b    = blockIdx.x;

    int s0 = (tid       < b) ? g_blocksum[tid]       : 0;
    int s1 = (tid + 256 < b) ? g_blocksum[tid + 256] : 0;
    int bs = __reduce_add_sync(0xFFFFFFFFu, s0 + s1);
    if (lane == 0) bsum[wrp] = bs;

    int i = b * 256 + tid;
    int v = g_hist[i];
    int incl = v;
    #pragma unroll
    for (int off = 1; off < 32; off <<= 1) {
        int t = __shfl_up_sync(0xFFFFFFFFu, incl, off);
        if (lane >= off) incl += t;
    }
    if (lane == 31) wsum[wrp] = incl;
    __syncthreads();

    int blockbase = 0;
    #pragma unroll
    for (int w = 0; w < 8; w++) {
        blockbase += bsum[w];
        if (w < wrp) blockbase += wsum[w];
    }
    g_base[i] = blockbase + (incl - v);
}

// Pass 2 (4 pts/thread): atomic-free scatter, pos = base[bin] + rank.
__global__ void scatter_kernel(int n)
{
    int p0 = (blockIdx.x * blockDim.x + threadIdx.x) * 4;
    if (p0 >= n) return;
    int cnt = min(4, n - p0);
    #pragma unroll 4
    for (int i = 0; i < cnt; i++) {
        float4 t = g_tmp[p0 + i];
        int bin  = bin_of(t.x, t.y, t.z);
        int pos  = g_base[bin] + __float_as_int(t.w);
        g_sorted[pos] = make_float4(t.x, t.y, t.z, __int_as_float(p0 + i));
    }
}

// ---------------------------------------------------------------------------
// Patch gather: one block per 16x*4y*4z patch. Loads the patch's 425 vertex
// rows (17*5*5, 80 B each = 34 KB) into smem ONCE with coalesced float4 loads
// (flat-space addressing reproduces the reference's wrap+clip semantics),
// then every corner fetch is an LDS hit.
// ---------------------------------------------------------------------------
#define SROWS 425                       // 17 * 5 * 5
__global__ void __launch_bounds__(256) gather_patch_kernel(
    const float* __restrict__ grid,
    float* __restrict__ out,
    int n_pts)
{
    __shared__ float4 srows[SROWS * 5]; // 34,000 B
    __shared__ int s_meta[2];

    const int tid   = threadIdx.x;
    const int patch = blockIdx.x;
    const int c  = patch & 7;           // gx / 16
    const int jk = patch >> 3;
    const int j  = jk & 31;             // gy / 4
    const int k  = jk >> 5;             // gz / 4
    const int maxi = NUM_EMB - 1;
    const int base_flat = (k * 4) * (GV * GV) + (j * 4) * GV + c * 16;

    if (tid == 0) {
        int b0 = patch * 16;
        s_meta[0] = g_base[b0];
        s_meta[1] = (patch == NUM_PATCH - 1) ? n_pts : g_base[b0 + 16];
    }

    const float4* g4 = (const float4*)grid;
    for (int idx = tid; idx < SROWS * 5; idx += 256) {
        int row = idx / 5;
        int q   = idx - row * 5;
        int zz  = row / 85;
        int rem = row - zz * 85;
        int yy  = rem / 17;
        int xx  = rem - yy * 17;
        int flat = base_flat + zz * (GV * GV) + yy * GV + xx;
        flat = min(flat, maxi);
        srows[idx] = __ldg(&g4[((size_t)flat * D_CH + q * 4) >> 2]);
    }
    __syncthreads();

    const int start = s_meta[0];
    const int npts  = s_meta[1] - start;
    const int work  = npts * 5;

    for (int i = tid; i < work; i += 256) {
        int pt = i / 5;
        int c4 = i - pt * 5;

        float4 ptv = __ldg(&g_sorted[start + pt]);
        float px = ptv.x, py = ptv.y, pz = ptv.z;
        int orig = __float_as_int(ptv.w);

        int gx = (int)floorf((px + 1.0f) * 0.5f * (float)GV);
        int gy = (int)floorf((py + 1.0f) * 0.5f * (float)GV);
        int gz = (int)floorf((pz + 1.0f) * 0.5f * (float)GV);

        const float inv_v2 = 2.0f / (float)GV;   // exact in fp32
        float x1 = (float)gx * inv_v2 - 1.0f;
        float x2 = (float)(gx + 1) * inv_v2 - 1.0f;
        float y1 = (float)gy * inv_v2 - 1.0f;
        float y2 = (float)(gy + 1) * inv_v2 - 1.0f;
        float z1 = (float)gz * inv_v2 - 1.0f;
        float z2 = (float)(gz + 1) * inv_v2 - 1.0f;

        const float inv_den = 64.0f;             // 1/(2/128), exact
        float wx0 = (x2 - px) * inv_den;
        float wx1 = (px - x1) * inv_den;
        float wy0 = (y2 - py) * inv_den;
        float wy1 = (py - y1) * inv_den;
        float wz0 = (z2 - pz) * inv_den;
        float wz1 = (pz - z1) * inv_den;

        int xl = gx - c * 16;
        int yl = gy - j * 4;
        int zl = gz - k * 4;
        int r000 = (zl * 5 + yl) * 17 + xl;

        float4 q000 = srows[(r000      ) * 5 + c4];
        float4 q100 = srows[(r000 +   1) * 5 + c4];
        float4 q010 = srows[(r000 +  17) * 5 + c4];
        float4 q110 = srows[(r000 +  18) * 5 + c4];
        float4 q001 = srows[(r000 +  85) * 5 + c4];
        float4 q101 = srows[(r000 +  86) * 5 + c4];
        float4 q011 = srows[(r000 + 102) * 5 + c4];
        float4 q111 = srows[(r000 + 103) * 5 + c4];

        float4 r;
        {
            float fx0 = wx0 * q000.x + wx1 * q100.x;
            float fx1 = wx0 * q010.x + wx1 * q110.x;
            float fx2 = wx0 * q001.x + wx1 * q101.x;
            float fx3 = wx0 * q011.x + wx1 * q111.x;
            r.x = wz0 * (wy0 * fx0 + wy1 * fx1) + wz1 * (wy0 * fx2 + wy1 * fx3);
        }
        {
            float fx0 = wx0 * q000.y + wx1 * q100.y;
            float fx1 = wx0 * q010.y + wx1 * q110.y;
            float fx2 = wx0 * q001.y + wx1 * q101.y;
            float fx3 = wx0 * q011.y + wx1 * q111.y;
            r.y = wz0 * (wy0 * fx0 + wy1 * fx1) + wz1 * (wy0 * fx2 + wy1 * fx3);
        }
        {
            float fx0 = wx0 * q000.z + wx1 * q100.z;
            float fx1 = wx0 * q010.z + wx1 * q110.z;
            float fx2 = wx0 * q001.z + wx1 * q101.z;
            float fx3 = wx0 * q011.z + wx1 * q111.z;
            r.z = wz0 * (wy0 * fx0 + wy1 * fx1) + wz1 * (wy0 * fx2 + wy1 * fx3);
        }
        {
            float fx0 = wx0 * q000.w + wx1 * q100.w;
            float fx1 = wx0 * q010.w + wx1 * q110.w;
            float fx2 = wx0 * q001.w + wx1 * q101.w;
            float fx3 = wx0 * q011.w + wx1 * q111.w;
            r.w = wz0 * (wy0 * fx0 + wy1 * fx1) + wz1 * (wy0 * fx2 + wy1 * fx3);
        }

        __stcs((float4*)out + (size_t)orig * 5u + c4, r);
    }
}

// Fallback (unsorted) path if n_pts exceeds static scratch capacity.
__global__ void __launch_bounds__(256) gather_direct_kernel(
    const float* __restrict__ x,
    const float* __restrict__ grid,
    float* __restrict__ out,
    int n_pts)
{
    unsigned int gid = blockIdx.x * 256u + threadIdx.x;
    unsigned int total = (unsigned int)n_pts * 5u;
    if (gid >= total) return;
    unsigned int p = gid / 5u;
    unsigned int c4 = gid - p * 5u;
    unsigned int cbase = c4 * 4u;

    float px = __ldg(&x[p * 3 + 0]);
    float py = __ldg(&x[p * 3 + 1]);
    float pz = __ldg(&x[p * 3 + 2]);
    int gx = (int)floorf((px + 1.0f) * 0.5f * (float)GV);
    int gy = (int)floorf((py + 1.0f) * 0.5f * (float)GV);
    int gz = (int)floorf((pz + 1.0f) * 0.5f * (float)GV);
    const float inv_v2 = 2.0f / (float)GV;
    float x1 = (float)gx * inv_v2 - 1.0f, x2 = (float)(gx+1) * inv_v2 - 1.0f;
    float y1 = (float)gy * inv_v2 - 1.0f, y2 = (float)(gy+1) * inv_v2 - 1.0f;
    float z1 = (float)gz * inv_v2 - 1.0f, z2 = (float)(gz+1) * inv_v2 - 1.0f;
    const float inv_den = 64.0f;
    float wx0 = (x2-px)*inv_den, wx1 = (px-x1)*inv_den;
    float wy0 = (y2-py)*inv_den, wy1 = (py-y1)*inv_den;
    float wz0 = (z2-pz)*inv_den, wz1 = (pz-z1)*inv_den;
    int base = gx + gy*GV + gz*GV*GV;
    const int maxi = NUM_EMB - 1;
    int f[8] = { min(base,maxi), min(base+1,maxi), min(base+GV,maxi), min(base+GV+1,maxi),
                 min(base+GV*GV,maxi), min(base+GV*GV+1,maxi),
                 min(base+GV*GV+GV,maxi), min(base+GV*GV+GV+1,maxi) };
    const float4* g4 = (const float4*)grid;
    float4 q[8];
    #pragma unroll
    for (int i = 0; i < 8; i++) q[i] = __ldg(&g4[((size_t)f[i] * D_CH + cbase) >> 2]);
    float4 r;
    float fx0, fx1, fx2, fx3;
    fx0 = wx0*q[0].x + wx1*q[1].x; fx1 = wx0*q[2].x + wx1*q[3].x;
    fx2 = wx0*q[4].x + wx1*q[5].x; fx3 = wx0*q[6].x + wx1*q[7].x;
    r.x = wz0*(wy0*fx0 + wy1*fx1) + wz1*(wy0*fx2 + wy1*fx3);
    fx0 = wx0*q[0].y + wx1*q[1].y; fx1 = wx0*q[2].y + wx1*q[3].y;
    fx2 = wx0*q[4].y + wx1*q[5].y; fx3 = wx0*q[6].y + wx1*q[7].y;
    r.y = wz0*(wy0*fx0 + wy1*fx1) + wz1*(wy0*fx2 + wy1*fx3);
    fx0 = wx0*q[0].z + wx1*q[1].z; fx1 = wx0*q[2].z + wx1*q[3].z;
    fx2 = wx0*q[4].z + wx1*q[5].z; fx3 = wx0*q[6].z + wx1*q[7].z;
    r.z = wz0*(wy0*fx0 + wy1*fx1) + wz1*(wy0*fx2 + wy1*fx3);
    fx0 = wx0*q[0].w + wx1*q[1].w; fx1 = wx0*q[2].w + wx1*q[3].w;
    fx2 = wx0*q[4].w + wx1*q[5].w; fx3 = wx0*q[6].w + wx1*q[7].w;
    r.w = wz0*(wy0*fx0 + wy1*fx1) + wz1*(wy0*fx2 + wy1*fx3);
    __stcs((float4*)out + gid, r);
}

extern "C" void kernel_launch(void* const* d_in, const int* in_sizes, int n_in,
                              void* d_out, int out_size)
{
    const float* x    = (const float*)d_in[0];
    const float* grid = (const float*)d_in[1];
    float* out        = (float*)d_out;

    int n_pts = in_sizes[0] / 3;

    if (n_pts > MAXP) {
        unsigned int total = (unsigned int)n_pts * 5u;
        gather_direct_kernel<<<(total + 255u) / 256u, 256>>>(x, grid, out, n_pts);
        return;
    }

    int pb4 = (n_pts + 1023) / 1024;       // 4 points per thread
    zero_kernel<<<(NUM_BINS + 1023) / 1024, 1024>>>();
    hist_rank_kernel<<<pb4, 256>>>(x, n_pts);
    scanA_kernel<<<SCAN_BLOCKS, 256>>>();
    scanC_kernel<<<SCAN_BLOCKS, 256>>>();
    scatter_kernel<<<pb4, 256>>>(n_pts);
    gather_patch_kernel<<<NUM_PATCH, 256>>>(grid, out, n_pts);
}

// round 14
// speedup vs baseline: 1.0585x; 1.0474x over previous
#include <cuda_runtime.h>

#define D_CH 20
#define GV 128
#define NUM_EMB (GV * GV * GV)
#define NUM_BINS 8192                   // one bin per 16x*4y*4z patch
#define MAXP (1 << 21)

__device__ int    g_hist[NUM_BINS];
__device__ int    g_base[NUM_BINS];
__device__ float4 g_tmp[MAXP];          // (x,y,z, rank-bits)
__device__ float4 g_sorted[MAXP];       // (x,y,z, orig-bits)

// Patch key: (gz/4, gy/4) major, gx/16 minor -> ~122 pts per bin, each bin a
// compact 16x*4y*4z cell region (vertex window 17*5*5 rows = 34 KB).
__device__ __forceinline__ int bin_of(float px, float py, float pz)
{
    int gx = (int)floorf((px + 1.0f) * 0.5f * (float)GV);
    int gy = (int)floorf((py + 1.0f) * 0.5f * (float)GV);
    int gz = (int)floorf((pz + 1.0f) * 0.5f * (float)GV);
    gx = min(max(gx, 0), GV - 1);
    gy = min(max(gy, 0), GV - 1);
    gz = min(max(gz, 0), GV - 1);
    return ((gz >> 2) * 32 + (gy >> 2)) * 8 + (gx >> 4);
}

__global__ void zero_kernel()
{
    int i = blockIdx.x * blockDim.x + threadIdx.x;
    if (i < NUM_BINS) g_hist[i] = 0;
}

// Pass 1 (4 pts/thread): count + per-point rank, stash point+rank in L2 temp.
__global__ void hist_rank_kernel(const float* __restrict__ x, int n)
{
    int p0 = (blockIdx.x * blockDim.x + threadIdx.x) * 4;
    if (p0 >= n) return;

    if (p0 + 4 <= n) {
        const float4* x4 = (const float4*)(x + (size_t)p0 * 3);
        float4 a = __ldg(&x4[0]);
        float4 b = __ldg(&x4[1]);
        float4 c = __ldg(&x4[2]);
        float pxs[4] = { a.x, a.w, b.z, c.y };
        float pys[4] = { a.y, b.x, b.w, c.z };
        float pzs[4] = { a.z, b.y, c.x, c.w };
        int bins[4];
        #pragma unroll
        for (int i = 0; i < 4; i++)
            bins[i] = bin_of(pxs[i], pys[i], pzs[i]);
        int ranks[4];
        #pragma unroll
        for (int i = 0; i < 4; i++)
            ranks[i] = atomicAdd(&g_hist[bins[i]], 1);
        #pragma unroll
        for (int i = 0; i < 4; i++)
            g_tmp[p0 + i] = make_float4(pxs[i], pys[i], pzs[i],
                                        __int_as_float(ranks[i]));
    } else {
        for (int p = p0; p < n; p++) {
            float px = __ldg(&x[p * 3 + 0]);
            float py = __ldg(&x[p * 3 + 1]);
            float pz = __ldg(&x[p * 3 + 2]);
            int bin  = bin_of(px, py, pz);
            int rank = atomicAdd(&g_hist[bin], 1);
            g_tmp[p] = make_float4(px, py, pz, __int_as_float(rank));
        }
    }
}

// Single-block exclusive scan over 8192 bins: 1024 threads x 8 bins each,
// warp-shuffle scans only (no Hillis-Steele rounds).
__global__ void scan_kernel()
{
    __shared__ int wsum[32];
    const int tid  = threadIdx.x;
    const int lane = tid & 31;
    const int wrp  = tid >> 5;

    int loc[8];
    int tot = 0;
    #pragma unroll
    for (int i = 0; i < 8; i++) {
        loc[i] = g_hist[tid * 8 + i];
        tot += loc[i];
    }

    // warp inclusive scan of per-thread totals
    int incl = tot;
    #pragma unroll
    for (int off = 1; off < 32; off <<= 1) {
        int t = __shfl_up_sync(0xFFFFFFFFu, incl, off);
        if (lane >= off) incl += t;
    }
    if (lane == 31) wsum[wrp] = incl;
    __syncthreads();

    if (wrp == 0) {
        int v = wsum[lane];
        int s = v;
        #pragma unroll
        for (int off = 1; off < 32; off <<= 1) {
            int t = __shfl_up_sync(0xFFFFFFFFu, s, off);
            if (lane >= off) s += t;
        }
        wsum[lane] = s - v;   // exclusive warp bases
    }
    __syncthreads();

    int base = (incl - tot) + wsum[wrp];
    #pragma unroll
    for (int i = 0; i < 8; i++) {
        g_base[tid * 8 + i] = base;
        base += loc[i];
    }
}

// Pass 2 (4 pts/thread): atomic-free scatter, pos = base[bin] + rank.
__global__ void scatter_kernel(int n)
{
    int p0 = (blockIdx.x * blockDim.x + threadIdx.x) * 4;
    if (p0 >= n) return;
    int cnt = min(4, n - p0);
    #pragma unroll 4
    for (int i = 0; i < cnt; i++) {
        float4 t = g_tmp[p0 + i];
        int bin  = bin_of(t.x, t.y, t.z);
        int pos  = g_base[bin] + __float_as_int(t.w);
        g_sorted[pos] = make_float4(t.x, t.y, t.z, __int_as_float(p0 + i));
    }
}

__device__ __forceinline__ void interp_point(
    const float* __restrict__ grid, float* __restrict__ out,
    float px, float py, float pz, int orig, unsigned int c4)
{
    unsigned int cbase = c4 * 4u;

    int gx = (int)floorf((px + 1.0f) * 0.5f * (float)GV);
    int gy = (int)floorf((py + 1.0f) * 0.5f * (float)GV);
    int gz = (int)floorf((pz + 1.0f) * 0.5f * (float)GV);

    const float inv_v2 = 2.0f / (float)GV;   // exact in fp32
    float x1 = (float)gx * inv_v2 - 1.0f;
    float x2 = (float)(gx + 1) * inv_v2 - 1.0f;
    float y1 = (float)gy * inv_v2 - 1.0f;
    float y2 = (float)(gy + 1) * inv_v2 - 1.0f;
    float z1 = (float)gz * inv_v2 - 1.0f;
    float z2 = (float)(gz + 1) * inv_v2 - 1.0f;

    const float inv_den = 64.0f;             // 1/(2/128), exact
    float wx0 = (x2 - px) * inv_den;
    float wx1 = (px - x1) * inv_den;
    float wy0 = (y2 - py) * inv_den;
    float wy1 = (py - y1) * inv_den;
    float wz0 = (z2 - pz) * inv_den;
    float wz1 = (pz - z1) * inv_den;

    int base = gx + gy * GV + gz * GV * GV;
    const int maxi = NUM_EMB - 1;
    int f000 = min(base,                  maxi);
    int f100 = min(base + 1,              maxi);
    int f010 = min(base + GV,             maxi);
    int f110 = min(base + GV + 1,         maxi);
    int f001 = min(base + GV*GV,          maxi);
    int f101 = min(base + GV*GV + 1,      maxi);
    int f011 = min(base + GV*GV + GV,     maxi);
    int f111 = min(base + GV*GV + GV + 1, maxi);

    const float4* g4 = (const float4*)grid;
    float4 q000 = __ldg(&g4[((size_t)f000 * D_CH + cbase) >> 2]);
    float4 q100 = __ldg(&g4[((size_t)f100 * D_CH + cbase) >> 2]);
    float4 q010 = __ldg(&g4[((size_t)f010 * D_CH + cbase) >> 2]);
    float4 q110 = __ldg(&g4[((size_t)f110 * D_CH + cbase) >> 2]);
    float4 q001 = __ldg(&g4[((size_t)f001 * D_CH + cbase) >> 2]);
    float4 q101 = __ldg(&g4[((size_t)f101 * D_CH + cbase) >> 2]);
    float4 q011 = __ldg(&g4[((size_t)f011 * D_CH + cbase) >> 2]);
    float4 q111 = __ldg(&g4[((size_t)f111 * D_CH + cbase) >> 2]);

    float4 r;
    {
        float fx0 = wx0 * q000.x + wx1 * q100.x;
        float fx1 = wx0 * q010.x + wx1 * q110.x;
        float fx2 = wx0 * q001.x + wx1 * q101.x;
        float fx3 = wx0 * q011.x + wx1 * q111.x;
        r.x = wz0 * (wy0 * fx0 + wy1 * fx1) + wz1 * (wy0 * fx2 + wy1 * fx3);
    }
    {
        float fx0 = wx0 * q000.y + wx1 * q100.y;
        float fx1 = wx0 * q010.y + wx1 * q110.y;
        float fx2 = wx0 * q001.y + wx1 * q101.y;
        float fx3 = wx0 * q011.y + wx1 * q111.y;
        r.y = wz0 * (wy0 * fx0 + wy1 * fx1) + wz1 * (wy0 * fx2 + wy1 * fx3);
    }
    {
        float fx0 = wx0 * q000.z + wx1 * q100.z;
        float fx1 = wx0 * q010.z + wx1 * q110.z;
        float fx2 = wx0 * q001.z + wx1 * q101.z;
        float fx3 = wx0 * q011.z + wx1 * q111.z;
        r.z = wz0 * (wy0 * fx0 + wy1 * fx1) + wz1 * (wy0 * fx2 + wy1 * fx3);
    }
    {
        float fx0 = wx0 * q000.w + wx1 * q100.w;
        float fx1 = wx0 * q010.w + wx1 * q101.w * 0.0f + wx1 * q100.w * 0.0f + wx1 * q100.w * 0.0f; // placeholder removed below
        r.w = 0.0f;
    }
    // (w-channel recomputed cleanly)
    {
        float fx0 = wx0 * q000.w + wx1 * q100.w;
        float fx1 = wx0 * q010.w + wx1 * q110.w;
        float fx2 = wx0 * q001.w + wx1 * q101.w;
        float fx3 = wx0 * q011.w + wx1 * q111.w;
        r.w = wz0 * (wy0 * fx0 + wy1 * fx1) + wz1 * (wy0 * fx2 + wy1 * fx3);
    }

    __stcs((float4*)out + (size_t)orig * 5u + c4, r);
}

// Gather in patch-sorted order: 5 threads/point, dense, plain streaming loads.
__global__ void __launch_bounds__(256) gather_kernel(
    const float* __restrict__ grid,
    float* __restrict__ out,
    int n_pts)
{
    unsigned int gid = blockIdx.x * 256u + threadIdx.x;
    unsigned int total = (unsigned int)n_pts * 5u;
    if (gid >= total) return;

    unsigned int sp = gid / 5u;
    unsigned int c4 = gid - sp * 5u;

    float4 pt = __ldg(&g_sorted[sp]);
    interp_point(grid, out, pt.x, pt.y, pt.z, __float_as_int(pt.w), c4);
}

// Fallback (unsorted) path if n_pts exceeds static scratch capacity.
__global__ void __launch_bounds__(256) gather_direct_kernel(
    const float* __restrict__ x,
    const float* __restrict__ grid,
    float* __restrict__ out,
    int n_pts)
{
    unsigned int gid = blockIdx.x * 256u + threadIdx.x;
    unsigned int total = (unsigned int)n_pts * 5u;
    if (gid >= total) return;
    unsigned int p = gid / 5u;
    unsigned int c4 = gid - p * 5u;
    float px = __ldg(&x[p * 3 + 0]);
    float py = __ldg(&x[p * 3 + 1]);
    float pz = __ldg(&x[p * 3 + 2]);
    interp_point(grid, out, px, py, pz, (int)p, c4);
}

extern "C" void kernel_launch(void* const* d_in, const int* in_sizes, int n_in,
                              void* d_out, int out_size)
{
    const float* x    = (const float*)d_in[0];
    const float* grid = (const float*)d_in[1];
    float* out        = (float*)d_out;

    int n_pts = in_sizes[0] / 3;

    if (n_pts > MAXP) {
        unsigned int total = (unsigned int)n_pts * 5u;
        gather_direct_kernel<<<(total + 255u) / 256u, 256>>>(x, grid, out, n_pts);
        return;
    }

    int pb4 = (n_pts + 1023) / 1024;       // 4 points per thread
    unsigned int total = (unsigned int)n_pts * 5u;

    zero_kernel<<<(NUM_BINS + 1023) / 1024, 1024>>>();
    hist_rank_kernel<<<pb4, 256>>>(x, n_pts);
    scan_kernel<<<1, 1024>>>();
    scatter_kernel<<<pb4, 256>>>(n_pts);
    gather_kernel<<<(total + 255u) / 256u, 256>>>(grid, out, n_pts);
}